// round 9
// baseline (speedup 1.0000x reference)
#include <cuda_runtime.h>
#include <stdint.h>
#include <math.h>

#define BATCH 32
#define NBOX  10647          // 507 + 2028 + 8112
#define KTOP  512
#define NBIN  4096
#define T13   (BATCH * 3 * 169)
#define V26   (BATCH * 3 * (676 / 4))
#define V52   (BATCH * 3 * (2704 / 4))
#define TVEC  (T13 + V26 + V52)

// ---------------- scratch (no allocation allowed) ----------------
__device__ float    g_boxes[BATCH * NBOX * 8];  // x1,y1,x2,y2,conf,cls,pad,pad
__device__ unsigned g_skey [BATCH * NBOX];      // mono32(score)

__device__ __forceinline__ float sigm(float x) {
    return 1.0f / (1.0f + expf(-x));
}

__device__ __forceinline__ void emit_box(int b, int n, float cx, float cy,
                                         float w_, float h_, float conf, int bcls)
{
    float4* bp = (float4*)(g_boxes + ((size_t)b * NBOX + n) * 8);
    bp[0] = make_float4(cx - 0.5f * w_, cy - 0.5f * h_, cx + 0.5f * w_, cy + 0.5f * h_);
    bp[1] = make_float4(conf, (float)bcls, 0.0f, 0.0f);
    g_skey[(size_t)b * NBOX + n] =
        (conf > 0.5f) ? (__float_as_uint(conf) | 0x80000000u) : 0x407FFFFFu;
}

// ---------------- decode: all 3 scales, one launch -----------------
// 13x13 scalar (HW=169 not %4); 26/52 vectorized float4 (4 cells/thread)
__global__ void __launch_bounds__(256)
decode_all_kernel(const float* __restrict__ o13, const float* __restrict__ o26,
                  const float* __restrict__ o52, const float* __restrict__ a13,
                  const float* __restrict__ a26, const float* __restrict__ a52)
{
    int gid = blockIdx.x * blockDim.x + threadIdx.x;
    if (gid >= TVEC) return;

    if (gid < T13) {
        // -------- scalar path, 13x13 --------
        const int HW = 169, W = 13;
        int r    = gid;
        int b    = r / (3 * HW);
        int q    = r - b * 3 * HW;
        int a    = q / HW;
        int cell = q - a * HW;
        int y    = cell / W;
        int x    = cell - y * W;

        const float* p = o13 + ((size_t)b * 255 + (size_t)a * 85) * HW + cell;
        float tx = p[0], ty = p[HW], tw = p[2 * HW], th = p[3 * HW], to = p[4 * HW];

        const float* pc = p + 5 * HW;
        float best = -3.402823466e38f;
        int   bcls = 0;
        #pragma unroll
        for (int f = 0; f < 80; f += 8) {
            float v0 = pc[(f + 0) * HW], v1 = pc[(f + 1) * HW];
            float v2 = pc[(f + 2) * HW], v3 = pc[(f + 3) * HW];
            float v4 = pc[(f + 4) * HW], v5 = pc[(f + 5) * HW];
            float v6 = pc[(f + 6) * HW], v7 = pc[(f + 7) * HW];
            float m01v = (v1 > v0) ? v1 : v0;  int m01i = (v1 > v0) ? f + 1 : f + 0;
            float m23v = (v3 > v2) ? v3 : v2;  int m23i = (v3 > v2) ? f + 3 : f + 2;
            float m45v = (v5 > v4) ? v5 : v4;  int m45i = (v5 > v4) ? f + 5 : f + 4;
            float m67v = (v7 > v6) ? v7 : v6;  int m67i = (v7 > v6) ? f + 7 : f + 6;
            float a03v = (m23v > m01v) ? m23v : m01v;  int a03i = (m23v > m01v) ? m23i : m01i;
            float a47v = (m67v > m45v) ? m67v : m45v;  int a47i = (m67v > m45v) ? m67i : m45i;
            float gv   = (a47v > a03v) ? a47v : a03v;  int gi   = (a47v > a03v) ? a47i : a03i;
            if (gv > best) { best = gv; bcls = gi; }
        }

        float conf = sigm(to);
        float cx   = ((float)x + sigm(tx)) * 32.0f;
        float cy   = ((float)y + sigm(ty)) * 32.0f;
        float w_   = a13[a * 2 + 0] * expf(tw);
        float h_   = a13[a * 2 + 1] * expf(th);
        emit_box(b, cell * 3 + a, cx, cy, w_, h_, conf, bcls);
        return;
    }

    // -------- vectorized path: 4 cells per thread --------
    const float* src; const float* anc;
    int HW, W, n_off, vid;
    float t;
    if (gid < T13 + V26) { vid = gid - T13;       src = o26; anc = a26; HW = 676;  W = 26; n_off = 507;  t = 16.0f; }
    else                 { vid = gid - T13 - V26; src = o52; anc = a52; HW = 2704; W = 52; n_off = 2535; t = 8.0f;  }

    int Q  = HW >> 2;
    int b  = vid / (3 * Q);
    int q  = vid - b * 3 * Q;
    int a  = q / Q;
    int c4 = q - a * Q;

    const float4* p = (const float4*)(src + ((size_t)b * 255 + (size_t)a * 85) * HW) + c4;

    float4 tx = p[0];
    float4 ty = p[(size_t)Q];
    float4 tw = p[(size_t)2 * Q];
    float4 th = p[(size_t)3 * Q];
    float4 to = p[(size_t)4 * Q];

    float4 bv = p[(size_t)5 * Q];
    int c0 = 0, c1 = 0, c2 = 0, c3 = 0;
    #pragma unroll 4
    for (int f = 6; f < 85; ++f) {
        float4 v = p[(size_t)f * Q];
        if (v.x > bv.x) { bv.x = v.x; c0 = f - 5; }
        if (v.y > bv.y) { bv.y = v.y; c1 = f - 5; }
        if (v.z > bv.z) { bv.z = v.z; c2 = f - 5; }
        if (v.w > bv.w) { bv.w = v.w; c3 = f - 5; }
    }

    float atx[4] = {tx.x, tx.y, tx.z, tx.w};
    float aty[4] = {ty.x, ty.y, ty.z, ty.w};
    float atw[4] = {tw.x, tw.y, tw.z, tw.w};
    float ath[4] = {th.x, th.y, th.z, th.w};
    float ato[4] = {to.x, to.y, to.z, to.w};
    int   acl[4] = {c0, c1, c2, c3};

    float aw = anc[a * 2 + 0];
    float ah = anc[a * 2 + 1];
    int cellbase = c4 << 2;
    #pragma unroll
    for (int u = 0; u < 4; ++u) {
        int cell = cellbase + u;
        int yq = cell / W;
        int xq = cell - yq * W;
        float conf = sigm(ato[u]);
        float cx = ((float)xq + sigm(atx[u])) * t;
        float cy = ((float)yq + sigm(aty[u])) * t;
        float w_ = aw * expf(atw[u]);
        float h_ = ah * expf(ath[u]);
        emit_box(b, n_off + cell * 3 + a, cx, cy, w_, h_, conf, acl[u]);
    }
}

// ======== fused: hist + select + rank + gather + sup + greedy, 1 CTA/batch ========
// dyn smem (sequential lifetimes):
//   [0,16384)      hist int[4096]     } live until end of rank
//   [16384,32768)  cum  int[4096]     }
//   [32768,49152)  cumw int[4096]
//   [49152,57344)  sel  u64[1024]
//   after rank:  sup u32[512*16] overlays [0,32768)
#define K2_SMEM 57344

__global__ void __launch_bounds__(1024, 1)
nms_kernel(float* __restrict__ out)
{
    extern __shared__ char dyn[];
    int*                hist = (int*)dyn;
    int*                cum  = (int*)(dyn + 16384);
    int*                cumw = (int*)(dyn + 32768);
    unsigned long long* sel  = (unsigned long long*)(dyn + 49152);
    unsigned*           sup  = (unsigned*)dyn;          // overlays hist+cum later

    __shared__ float sx1[KTOP], sy1[KTOP], sx2[KTOP], sy2[KTOP], sar[KTOP];
    __shared__ unsigned char scl[KTOP];
    __shared__ int      wsum[32];
    __shared__ int      s_B;
    __shared__ unsigned validw[16], keepw[16];

    int b    = blockIdx.x;
    int tid  = threadIdx.x;
    int lane = tid & 31;
    int wid  = tid >> 5;
    const unsigned* gk = g_skey + (size_t)b * NBOX;

    #pragma unroll
    for (int i = tid; i < NBIN; i += 1024) hist[i] = 0;
    if (tid == 0) s_B = 0;
    if (tid < 16) { validw[tid] = 0u; keepw[tid] = 0u; }
    __syncthreads();

    // ---- histogram over mantissa bits [11,23) of passing scores ----
    for (int i = tid; i < NBOX; i += 1024) {
        unsigned sk = gk[i];
        if (sk > 0xBF000000u)                       // conf > 0.5 strictly
            atomicAdd(&hist[(sk >> 11) & 0xFFFu], 1);
    }
    __syncthreads();

    // ---- descending exclusive cumsum + boundary bin ----
    {
        int hi = NBIN - 1 - 4 * tid;                // thread covers hi..hi-3 (desc)
        int h0 = hist[hi], h1 = hist[hi - 1], h2 = hist[hi - 2], h3 = hist[hi - 3];
        int s4 = h0 + h1 + h2 + h3;
        int pfx = s4;
        #pragma unroll
        for (int d = 1; d < 32; d <<= 1) {
            int v = __shfl_up_sync(0xffffffffu, pfx, d);
            if (lane >= d) pfx += v;
        }
        if (lane == 31) wsum[wid] = pfx;
        __syncthreads();
        if (tid < 32) {
            int v = wsum[lane];
            int p = v;
            #pragma unroll
            for (int d = 1; d < 32; d <<= 1) {
                int u = __shfl_up_sync(0xffffffffu, p, d);
                if (lane >= d) p += u;
            }
            wsum[lane] = p - v;                     // exclusive over warps
        }
        __syncthreads();
        int excl = wsum[wid] + (pfx - s4);          // # keys in bins > hi
        cum[hi]     = excl;                cumw[hi]     = excl;
        cum[hi - 1] = excl + h0;           cumw[hi - 1] = excl + h0;
        cum[hi - 2] = excl + h0 + h1;      cumw[hi - 2] = excl + h0 + h1;
        cum[hi - 3] = excl + h0 + h1 + h2; cumw[hi - 3] = excl + h0 + h1 + h2;
        if (excl < KTOP && excl + s4 >= KTOP) {
            int c = excl;
            if      (c + h0 >= KTOP)           s_B = hi;
            else if (c + h0 + h1 >= KTOP)      s_B = hi - 1;
            else if (c + h0 + h1 + h2 >= KTOP) s_B = hi - 2;
            else                               s_B = hi - 3;
        }
    }
    __syncthreads();
    int Bbin = s_B;

    // ---- scatter passing keys to bin-sorted slots ----
    for (int i = tid; i < NBOX; i += 1024) {
        unsigned sk = gk[i];
        if (sk > 0xBF000000u) {
            int bin = (sk >> 11) & 0xFFFu;
            if (bin >= Bbin) {
                int slot = atomicAdd(&cumw[bin], 1);
                if (slot < 1024)
                    sel[slot] = ((unsigned long long)sk << 32) |
                                (unsigned long long)(0xFFFFFFFFu - (unsigned)i);
            }
        }
    }
    __syncthreads();

    // ---- exact rank = base + intra-bin compares (avg ~1.3) + gather ----
    int C = cum[Bbin] + hist[Bbin];
    if (C > 1024) C = 1024;
    if (tid < C) {
        unsigned long long key = sel[tid];
        int bin  = (int)((key >> 43) & 0xFFFull);
        int base = cum[bin];
        int cnt  = hist[bin];
        int end  = base + cnt; if (end > 1024) end = 1024;
        int rank = base;
        for (int j = base; j < end; ++j) rank += (sel[j] > key);
        if (rank < KTOP) {
            unsigned idx = 0xFFFFFFFFu - (unsigned)(key & 0xFFFFFFFFull);
            const float4* sp = (const float4*)(g_boxes + ((size_t)b * NBOX + idx) * 8);
            float4 p0 = sp[0], p1 = sp[1];
            sx1[rank] = p0.x; sy1[rank] = p0.y; sx2[rank] = p0.z; sy2[rank] = p0.w;
            sar[rank] = (p0.z - p0.x) * (p0.w - p0.y);
            scl[rank] = (unsigned char)(int)p1.y;
            float* dst = out + ((size_t)b * KTOP + rank) * 7;
            dst[0] = p0.x; dst[1] = p0.y; dst[2] = p0.z; dst[3] = p0.w;
            dst[4] = p1.x; dst[5] = p1.y;
            if (p1.x > 0.5f) atomicOr(&validw[rank >> 5], 1u << (rank & 31));
        }
    }
    __syncthreads();     // hist/cum/sel dead past here; sup overlays them

    // ---- forward-only suppress bitmatrix (8 words/thread) ----
    #pragma unroll
    for (int w = tid; w < KTOP * 16; w += 1024) {
        int i  = w >> 4;
        int wj = w & 15;
        int j0 = wj << 5;
        unsigned fwd;
        if (j0 + 31 <= i)      fwd = 0u;
        else if (j0 > i)       fwd = 0xFFFFFFFFu;
        else                   fwd = 0xFFFFFFFFu << (i - j0 + 1);

        unsigned res = 0u;
        if (fwd) {
            unsigned ci4 = (unsigned)scl[i] * 0x01010101u;
            const unsigned* cp = (const unsigned*)(scl + j0);
            unsigned bits = 0u;
            #pragma unroll
            for (int qq = 0; qq < 8; ++qq) {
                unsigned eq = __vcmpeq4(cp[qq], ci4);
                unsigned bq = (((eq & 0x01010101u) * 0x01020408u) >> 24) & 0xFu;
                bits |= bq << (qq * 4);
            }
            bits &= fwd;
            if (bits) {
                float x1i = sx1[i], y1i = sy1[i], x2i = sx2[i], y2i = sy2[i];
                float ai  = sar[i];
                while (bits) {
                    int jj = __ffs(bits) - 1; bits &= bits - 1;
                    int j = j0 + jj;
                    float ix1 = fmaxf(x1i, sx1[j]);
                    float iy1 = fmaxf(y1i, sy1[j]);
                    float ix2 = fminf(x2i, sx2[j]);
                    float iy2 = fminf(y2i, sy2[j]);
                    float inter = fmaxf(ix2 - ix1, 0.0f) * fmaxf(iy2 - iy1, 0.0f);
                    float iou = inter / (ai + sar[j] - inter + 1e-9f);
                    if (iou > 0.3f) res |= 1u << jj;
                }
            }
        }
        sup[w] = res;
    }
    __syncthreads();

    // ---- chunked greedy scan (warp 0) ----
    if (tid < 32) {
        unsigned cand  = (lane < 16) ? validw[lane] : 0u;
        unsigned keepv = 0u;
        for (int blk = 0; blk < 16; ++blk) {
            unsigned cw = __shfl_sync(0xffffffffu, cand, blk);
            int base = blk << 5;
            unsigned rw = sup[(base + lane) * 16 + blk];   // row base+lane, word blk
            unsigned k32 = 0u;
            #pragma unroll 1
            for (int g = 0; g < 32; g += 8) {
                unsigned s0 = __shfl_sync(0xffffffffu, rw, g + 0);
                unsigned s1 = __shfl_sync(0xffffffffu, rw, g + 1);
                unsigned s2 = __shfl_sync(0xffffffffu, rw, g + 2);
                unsigned s3 = __shfl_sync(0xffffffffu, rw, g + 3);
                unsigned s4 = __shfl_sync(0xffffffffu, rw, g + 4);
                unsigned s5 = __shfl_sync(0xffffffffu, rw, g + 5);
                unsigned s6 = __shfl_sync(0xffffffffu, rw, g + 6);
                unsigned s7 = __shfl_sync(0xffffffffu, rw, g + 7);
                if (cw & (1u << (g + 0))) { k32 |= 1u << (g + 0); cw &= ~s0; }
                if (cw & (1u << (g + 1))) { k32 |= 1u << (g + 1); cw &= ~s1; }
                if (cw & (1u << (g + 2))) { k32 |= 1u << (g + 2); cw &= ~s2; }
                if (cw & (1u << (g + 3))) { k32 |= 1u << (g + 3); cw &= ~s3; }
                if (cw & (1u << (g + 4))) { k32 |= 1u << (g + 4); cw &= ~s4; }
                if (cw & (1u << (g + 5))) { k32 |= 1u << (g + 5); cw &= ~s5; }
                if (cw & (1u << (g + 6))) { k32 |= 1u << (g + 6); cw &= ~s6; }
                if (cw & (1u << (g + 7))) { k32 |= 1u << (g + 7); cw &= ~s7; }
            }
            // dense apply: 32 independent masked loads
            unsigned acc = 0u;
            if (lane < 16) {
                #pragma unroll
                for (int j = 0; j < 32; ++j) {
                    unsigned m = 0u - ((k32 >> j) & 1u);
                    acc |= sup[(base + j) * 16 + lane] & m;
                }
            }
            if (lane > blk && lane < 16) cand &= ~acc;
            if (lane == blk) keepv = k32;
        }
        if (lane < 16) keepw[lane] = keepv;
    }
    __syncthreads();

    if (tid < KTOP) {
        bool k = (keepw[tid >> 5] >> (tid & 31)) & 1u;
        out[((size_t)b * KTOP + tid) * 7 + 6] = k ? 1.0f : 0.0f;
    }
}

// ---------------- launch ------------------------------------------
extern "C" void kernel_launch(void* const* d_in, const int* in_sizes, int n_in,
                              void* d_out, int out_size)
{
    const float* out13 = (const float*)d_in[0];
    const float* out26 = (const float*)d_in[1];
    const float* out52 = (const float*)d_in[2];
    const float* anc13 = (const float*)d_in[3];
    const float* anc26 = (const float*)d_in[4];
    const float* anc52 = (const float*)d_in[5];
    float* out = (float*)d_out;

    const int TPB = 256;
    decode_all_kernel<<<(TVEC + TPB - 1) / TPB, TPB>>>(out13, out26, out52,
                                                       anc13, anc26, anc52);

    static bool attr_set = false;
    if (!attr_set) {
        cudaFuncSetAttribute(nms_kernel,
                             cudaFuncAttributeMaxDynamicSharedMemorySize, K2_SMEM);
        attr_set = true;
    }
    nms_kernel<<<BATCH, 1024, K2_SMEM>>>(out);
}

// round 10
// speedup vs baseline: 1.1073x; 1.1073x over previous
#include <cuda_runtime.h>
#include <stdint.h>
#include <math.h>

#define BATCH 32
#define NBOX  10647          // 507 + 2028 + 8112
#define NBPAD 10648          // padded stride (16B-aligned uint4 rows)
#define KTOP  512
#define NBIN  4096
#define TTOT  (BATCH * 3 * (169 + 676 + 2704))
#define T13   (BATCH * 3 * 169)
#define T26   (BATCH * 3 * 676)

// ---------------- scratch (no allocation allowed) ----------------
__device__ float    g_boxes[BATCH * NBOX * 8];  // x1,y1,x2,y2,conf,cls,pad,pad
__device__ unsigned g_skey [BATCH * NBPAD];     // mono32(score); pad elem stays 0
__device__ int      g_hist [BATCH * NBIN];      // zero at rest; decode fills, nms clears
__device__ unsigned g_valid[BATCH * 16];

__device__ __forceinline__ float sigm(float x) {
    return 1.0f / (1.0f + expf(-x));
}

// ---------------- decode: all 3 scales, one launch, + global hist --
__global__ void __launch_bounds__(256)
decode_all_kernel(const float* __restrict__ o13, const float* __restrict__ o26,
                  const float* __restrict__ o52, const float* __restrict__ a13,
                  const float* __restrict__ a26, const float* __restrict__ a52)
{
    int gid = blockIdx.x * blockDim.x + threadIdx.x;
    if (gid >= TTOT) return;

    const float* src; const float* anc;
    int HW, W, n_off, r;
    float t;
    if (gid < T13)            { r = gid;             src = o13; anc = a13; HW = 169;  W = 13; n_off = 0;    t = 32.0f; }
    else if (gid < T13 + T26) { r = gid - T13;       src = o26; anc = a26; HW = 676;  W = 26; n_off = 507;  t = 16.0f; }
    else                      { r = gid - T13 - T26; src = o52; anc = a52; HW = 2704; W = 52; n_off = 2535; t = 8.0f;  }

    int b    = r / (3 * HW);
    int q    = r - b * 3 * HW;
    int a    = q / HW;
    int cell = q - a * HW;
    int y    = cell / W;
    int x    = cell - y * W;

    const float* p = src + ((size_t)b * 255 + (size_t)a * 85) * HW + cell;

    float tx = p[0];
    float ty = p[(size_t)HW];
    float tw = p[(size_t)2 * HW];
    float th = p[(size_t)3 * HW];
    float to = p[(size_t)4 * HW];

    // argmax over 80 classes, pairwise-tree per group of 8 (first-occurrence ties)
    const float* pc = p + (size_t)5 * HW;
    float best = -3.402823466e38f;
    int   bcls = 0;
    #pragma unroll
    for (int f = 0; f < 80; f += 8) {
        float v0 = pc[(size_t)(f + 0) * HW];
        float v1 = pc[(size_t)(f + 1) * HW];
        float v2 = pc[(size_t)(f + 2) * HW];
        float v3 = pc[(size_t)(f + 3) * HW];
        float v4 = pc[(size_t)(f + 4) * HW];
        float v5 = pc[(size_t)(f + 5) * HW];
        float v6 = pc[(size_t)(f + 6) * HW];
        float v7 = pc[(size_t)(f + 7) * HW];
        float m01v = (v1 > v0) ? v1 : v0;  int m01i = (v1 > v0) ? f + 1 : f + 0;
        float m23v = (v3 > v2) ? v3 : v2;  int m23i = (v3 > v2) ? f + 3 : f + 2;
        float m45v = (v5 > v4) ? v5 : v4;  int m45i = (v5 > v4) ? f + 5 : f + 4;
        float m67v = (v7 > v6) ? v7 : v6;  int m67i = (v7 > v6) ? f + 7 : f + 6;
        float a03v = (m23v > m01v) ? m23v : m01v;  int a03i = (m23v > m01v) ? m23i : m01i;
        float a47v = (m67v > m45v) ? m67v : m45v;  int a47i = (m67v > m45v) ? m67i : m45i;
        float gv   = (a47v > a03v) ? a47v : a03v;  int gi   = (a47v > a03v) ? a47i : a03i;
        if (gv > best) { best = gv; bcls = gi; }
    }

    float conf = sigm(to);
    float cx   = ((float)x + sigm(tx)) * t;
    float cy   = ((float)y + sigm(ty)) * t;
    float w_   = anc[a * 2 + 0] * expf(tw);
    float h_   = anc[a * 2 + 1] * expf(th);

    int n = n_off + cell * 3 + a;
    float4* bp = (float4*)(g_boxes + ((size_t)b * NBOX + n) * 8);
    bp[0] = make_float4(cx - 0.5f * w_, cy - 0.5f * h_, cx + 0.5f * w_, cy + 0.5f * h_);
    bp[1] = make_float4(conf, (float)bcls, 0.0f, 0.0f);

    unsigned sk = (conf > 0.5f) ? (__float_as_uint(conf) | 0x80000000u) : 0x407FFFFFu;
    g_skey[(size_t)b * NBPAD + n] = sk;
    if (conf > 0.5f)
        atomicAdd(&g_hist[b * NBIN + ((sk >> 11) & 0xFFFu)], 1);
}

// ======== K2: load hist + cumsum + scatter(u4) + rank + gather ========
// dyn smem: hist int[4096] @0, cum @16384, cumw @32768, sel u64[1024] @49152
#define K2_SMEM 57344

__global__ void __launch_bounds__(1024, 1)
select_rank_kernel(float* __restrict__ out)
{
    extern __shared__ char dyn[];
    int*                hist = (int*)dyn;
    int*                cum  = (int*)(dyn + 16384);
    int*                cumw = (int*)(dyn + 32768);
    unsigned long long* sel  = (unsigned long long*)(dyn + 49152);

    __shared__ int      wsum[32];
    __shared__ int      s_B;
    __shared__ unsigned validw[16];

    int b    = blockIdx.x;
    int tid  = threadIdx.x;
    int lane = tid & 31;
    int wid  = tid >> 5;

    // ---- load per-batch histogram (built by decode) ----
    const int* gh = g_hist + b * NBIN;
    #pragma unroll
    for (int i = tid; i < NBIN; i += 1024) hist[i] = gh[i];
    if (tid == 0) s_B = 0;
    if (tid < 16) validw[tid] = 0u;
    __syncthreads();

    // ---- descending exclusive cumsum + boundary bin ----
    {
        int hi = NBIN - 1 - 4 * tid;                // thread covers hi..hi-3 (desc)
        int h0 = hist[hi], h1 = hist[hi - 1], h2 = hist[hi - 2], h3 = hist[hi - 3];
        int s4 = h0 + h1 + h2 + h3;
        int pfx = s4;
        #pragma unroll
        for (int d = 1; d < 32; d <<= 1) {
            int v = __shfl_up_sync(0xffffffffu, pfx, d);
            if (lane >= d) pfx += v;
        }
        if (lane == 31) wsum[wid] = pfx;
        __syncthreads();
        if (tid < 32) {
            int v = wsum[lane];
            int p = v;
            #pragma unroll
            for (int d = 1; d < 32; d <<= 1) {
                int u = __shfl_up_sync(0xffffffffu, p, d);
                if (lane >= d) p += u;
            }
            wsum[lane] = p - v;                     // exclusive over warps
        }
        __syncthreads();
        int excl = wsum[wid] + (pfx - s4);          // # keys in bins > hi
        cum[hi]     = excl;                cumw[hi]     = excl;
        cum[hi - 1] = excl + h0;           cumw[hi - 1] = excl + h0;
        cum[hi - 2] = excl + h0 + h1;      cumw[hi - 2] = excl + h0 + h1;
        cum[hi - 3] = excl + h0 + h1 + h2; cumw[hi - 3] = excl + h0 + h1 + h2;
        if (excl < KTOP && excl + s4 >= KTOP) {
            int c = excl;
            if      (c + h0 >= KTOP)           s_B = hi;
            else if (c + h0 + h1 >= KTOP)      s_B = hi - 1;
            else if (c + h0 + h1 + h2 >= KTOP) s_B = hi - 2;
            else                               s_B = hi - 3;
        }
    }
    __syncthreads();
    int Bbin = s_B;

    // ---- scatter passing keys to bin-sorted slots (uint4 reads) ----
    const uint4* gk4 = (const uint4*)(g_skey + (size_t)b * NBPAD);
    for (int i4 = tid; i4 < NBPAD / 4; i4 += 1024) {
        uint4 kv = gk4[i4];
        int ib = i4 << 2;
        unsigned ks[4] = {kv.x, kv.y, kv.z, kv.w};
        #pragma unroll
        for (int u = 0; u < 4; ++u) {
            unsigned sk = ks[u];
            int i = ib + u;                          // i==NBOX pad has sk==0 -> fails
            if (sk > 0xBF000000u) {
                int bin = (sk >> 11) & 0xFFFu;
                if (bin >= Bbin) {
                    int slot = atomicAdd(&cumw[bin], 1);
                    if (slot < 1024)
                        sel[slot] = ((unsigned long long)sk << 32) |
                                    (unsigned long long)(0xFFFFFFFFu - (unsigned)i);
                }
            }
        }
    }
    __syncthreads();

    // ---- exact rank = base + intra-bin compares (avg ~1.3) + gather ----
    int C = cum[Bbin] + hist[Bbin];
    if (C > 1024) C = 1024;
    if (tid < C) {
        unsigned long long key = sel[tid];
        int bin  = (int)((key >> 43) & 0xFFFull);
        int base = cum[bin];
        int cnt  = hist[bin];
        int end  = base + cnt; if (end > 1024) end = 1024;
        int rank = base;
        for (int j = base; j < end; ++j) rank += (sel[j] > key);
        if (rank < KTOP) {
            unsigned idx = 0xFFFFFFFFu - (unsigned)(key & 0xFFFFFFFFull);
            const float4* sp = (const float4*)(g_boxes + ((size_t)b * NBOX + idx) * 8);
            float4 p0 = sp[0], p1 = sp[1];
            float* dst = out + ((size_t)b * KTOP + rank) * 7;
            dst[0] = p0.x; dst[1] = p0.y; dst[2] = p0.z; dst[3] = p0.w;
            dst[4] = p1.x; dst[5] = p1.y;
            if (p1.x > 0.5f) atomicOr(&validw[rank >> 5], 1u << (rank & 31));
        }
    }
    __syncthreads();
    if (tid < 16) g_valid[b * 16 + tid] = validw[tid];
}

// ======== K3: sup bitmatrix + greedy, one CTA per batch ========
__global__ void __launch_bounds__(1024, 1)
nms_kernel(float* __restrict__ out)
{
    __shared__ float sx1[KTOP], sy1[KTOP], sx2[KTOP], sy2[KTOP], sar[KTOP];
    __shared__ unsigned char scl[KTOP];
    __shared__ unsigned sup[KTOP * 16];     // 32 KB
    __shared__ unsigned validw[16], keepw[16];

    int b    = blockIdx.x;
    int tid  = threadIdx.x;
    int lane = tid & 31;
    const float* base_row = out + (size_t)b * KTOP * 7;

    if (tid < KTOP) {
        const float* r = base_row + (size_t)tid * 7;
        float x1 = r[0], y1 = r[1], x2 = r[2], y2 = r[3];
        sx1[tid] = x1; sy1[tid] = y1; sx2[tid] = x2; sy2[tid] = y2;
        sar[tid] = (x2 - x1) * (y2 - y1);
        scl[tid] = (unsigned char)(int)r[5];
    }
    if (tid < 16) { validw[tid] = g_valid[b * 16 + tid]; keepw[tid] = 0u; }
    __syncthreads();

    // ---- forward-only suppress bitmatrix (8 words/thread) ----
    #pragma unroll
    for (int w = tid; w < KTOP * 16; w += 1024) {
        int i  = w >> 4;
        int wj = w & 15;
        int j0 = wj << 5;
        unsigned fwd;
        if (j0 + 31 <= i)      fwd = 0u;
        else if (j0 > i)       fwd = 0xFFFFFFFFu;
        else                   fwd = 0xFFFFFFFFu << (i - j0 + 1);

        unsigned res = 0u;
        if (fwd) {
            unsigned ci4 = (unsigned)scl[i] * 0x01010101u;
            const unsigned* cp = (const unsigned*)(scl + j0);
            unsigned bits = 0u;
            #pragma unroll
            for (int qq = 0; qq < 8; ++qq) {
                unsigned eq = __vcmpeq4(cp[qq], ci4);
                unsigned bq = (((eq & 0x01010101u) * 0x01020408u) >> 24) & 0xFu;
                bits |= bq << (qq * 4);
            }
            bits &= fwd;
            if (bits) {
                float x1i = sx1[i], y1i = sy1[i], x2i = sx2[i], y2i = sy2[i];
                float ai  = sar[i];
                while (bits) {
                    int jj = __ffs(bits) - 1; bits &= bits - 1;
                    int j = j0 + jj;
                    float ix1 = fmaxf(x1i, sx1[j]);
                    float iy1 = fmaxf(y1i, sy1[j]);
                    float ix2 = fminf(x2i, sx2[j]);
                    float iy2 = fminf(y2i, sy2[j]);
                    float inter = fmaxf(ix2 - ix1, 0.0f) * fmaxf(iy2 - iy1, 0.0f);
                    float iou = inter / (ai + sar[j] - inter + 1e-9f);
                    if (iou > 0.3f) res |= 1u << jj;
                }
            }
        }
        sup[w] = res;
    }
    __syncthreads();

    // ---- chunked greedy scan (warp 0) ----
    if (tid < 32) {
        unsigned cand  = (lane < 16) ? validw[lane] : 0u;
        unsigned keepv = 0u;
        for (int blk = 0; blk < 16; ++blk) {
            unsigned cw = __shfl_sync(0xffffffffu, cand, blk);
            int base = blk << 5;
            unsigned rw = sup[(base + lane) * 16 + blk];   // row base+lane, word blk
            unsigned k32 = 0u;
            #pragma unroll 1
            for (int g = 0; g < 32; g += 8) {
                unsigned s0 = __shfl_sync(0xffffffffu, rw, g + 0);
                unsigned s1 = __shfl_sync(0xffffffffu, rw, g + 1);
                unsigned s2 = __shfl_sync(0xffffffffu, rw, g + 2);
                unsigned s3 = __shfl_sync(0xffffffffu, rw, g + 3);
                unsigned s4 = __shfl_sync(0xffffffffu, rw, g + 4);
                unsigned s5 = __shfl_sync(0xffffffffu, rw, g + 5);
                unsigned s6 = __shfl_sync(0xffffffffu, rw, g + 6);
                unsigned s7 = __shfl_sync(0xffffffffu, rw, g + 7);
                if (cw & (1u << (g + 0))) { k32 |= 1u << (g + 0); cw &= ~s0; }
                if (cw & (1u << (g + 1))) { k32 |= 1u << (g + 1); cw &= ~s1; }
                if (cw & (1u << (g + 2))) { k32 |= 1u << (g + 2); cw &= ~s2; }
                if (cw & (1u << (g + 3))) { k32 |= 1u << (g + 3); cw &= ~s3; }
                if (cw & (1u << (g + 4))) { k32 |= 1u << (g + 4); cw &= ~s4; }
                if (cw & (1u << (g + 5))) { k32 |= 1u << (g + 5); cw &= ~s5; }
                if (cw & (1u << (g + 6))) { k32 |= 1u << (g + 6); cw &= ~s6; }
                if (cw & (1u << (g + 7))) { k32 |= 1u << (g + 7); cw &= ~s7; }
            }
            // dense apply: 32 independent masked loads
            unsigned acc = 0u;
            if (lane < 16) {
                #pragma unroll
                for (int j = 0; j < 32; ++j) {
                    unsigned m = 0u - ((k32 >> j) & 1u);
                    acc |= sup[(base + j) * 16 + lane] & m;
                }
            }
            if (lane > blk && lane < 16) cand &= ~acc;
            if (lane == blk) keepv = k32;
        }
        if (lane < 16) keepw[lane] = keepv;
    }
    __syncthreads();

    if (tid < KTOP) {
        bool k = (keepw[tid >> 5] >> (tid & 31)) & 1u;
        out[((size_t)b * KTOP + tid) * 7 + 6] = k ? 1.0f : 0.0f;
    }

    // ---- restore g_hist=0 for the next (graph-replayed) run ----
    int* gh = g_hist + b * NBIN;
    #pragma unroll
    for (int i = tid; i < NBIN; i += 1024) gh[i] = 0;
}

// ---------------- launch ------------------------------------------
extern "C" void kernel_launch(void* const* d_in, const int* in_sizes, int n_in,
                              void* d_out, int out_size)
{
    const float* out13 = (const float*)d_in[0];
    const float* out26 = (const float*)d_in[1];
    const float* out52 = (const float*)d_in[2];
    const float* anc13 = (const float*)d_in[3];
    const float* anc26 = (const float*)d_in[4];
    const float* anc52 = (const float*)d_in[5];
    float* out = (float*)d_out;

    const int TPB = 256;
    decode_all_kernel<<<(TTOT + TPB - 1) / TPB, TPB>>>(out13, out26, out52,
                                                       anc13, anc26, anc52);

    static bool attr_set = false;
    if (!attr_set) {
        cudaFuncSetAttribute(select_rank_kernel,
                             cudaFuncAttributeMaxDynamicSharedMemorySize, K2_SMEM);
        attr_set = true;
    }
    select_rank_kernel<<<BATCH, 1024, K2_SMEM>>>(out);
    nms_kernel<<<BATCH, 1024>>>(out);
}

// round 11
// speedup vs baseline: 1.1795x; 1.0652x over previous
#include <cuda_runtime.h>
#include <stdint.h>
#include <math.h>

#define BATCH 32
#define NBOX  10647          // 507 + 2028 + 8112
#define NBPAD 10648          // padded stride (16B-aligned uint4 rows)
#define KTOP  512
#define NBIN  4096
#define TTOT  (BATCH * 3 * (169 + 676 + 2704))
#define T13   (BATCH * 3 * 169)
#define T26   (BATCH * 3 * 676)

// ---------------- scratch (no allocation allowed) ----------------
__device__ float    g_boxes[BATCH * NBOX * 8];  // x1,y1,x2,y2,conf,cls,pad,pad
__device__ unsigned g_skey [BATCH * NBPAD];     // mono32(score); pad elem stays 0
__device__ int      g_hist [BATCH * NBIN];      // zero at rest; decode fills, nms clears
__device__ unsigned g_valid[BATCH * 16];

__device__ __forceinline__ float sigm(float x) {
    return 1.0f / (1.0f + expf(-x));
}

// ---------------- compile-time specialized per-scale decode -------
// HW/W/NOFF constexpr -> all 85 channel loads use immediate offsets (no IMAD)
template <int HW, int W, int NOFF>
__device__ __forceinline__ void decode_scale(const float* __restrict__ src,
                                             const float* __restrict__ anc,
                                             int r, float t)
{
    int b    = r / (3 * HW);
    int q    = r - b * 3 * HW;
    int a    = q / HW;
    int cell = q - a * HW;
    int y    = cell / W;
    int x    = cell - y * W;

    const float* p = src + ((size_t)b * 255 + (size_t)a * 85) * HW + cell;

    float tx = p[0];
    float ty = p[HW];
    float tw = p[2 * HW];
    float th = p[3 * HW];
    float to = p[4 * HW];

    // argmax over 80 classes, pairwise-tree per group of 8 (first-occurrence ties)
    const float* pc = p + 5 * HW;
    float best = -3.402823466e38f;
    int   bcls = 0;
    #pragma unroll
    for (int f = 0; f < 80; f += 8) {
        float v0 = pc[(f + 0) * HW];
        float v1 = pc[(f + 1) * HW];
        float v2 = pc[(f + 2) * HW];
        float v3 = pc[(f + 3) * HW];
        float v4 = pc[(f + 4) * HW];
        float v5 = pc[(f + 5) * HW];
        float v6 = pc[(f + 6) * HW];
        float v7 = pc[(f + 7) * HW];
        float m01v = (v1 > v0) ? v1 : v0;  int m01i = (v1 > v0) ? f + 1 : f + 0;
        float m23v = (v3 > v2) ? v3 : v2;  int m23i = (v3 > v2) ? f + 3 : f + 2;
        float m45v = (v5 > v4) ? v5 : v4;  int m45i = (v5 > v4) ? f + 5 : f + 4;
        float m67v = (v7 > v6) ? v7 : v6;  int m67i = (v7 > v6) ? f + 7 : f + 6;
        float a03v = (m23v > m01v) ? m23v : m01v;  int a03i = (m23v > m01v) ? m23i : m01i;
        float a47v = (m67v > m45v) ? m67v : m45v;  int a47i = (m67v > m45v) ? m67i : m45i;
        float gv   = (a47v > a03v) ? a47v : a03v;  int gi   = (a47v > a03v) ? a47i : a03i;
        if (gv > best) { best = gv; bcls = gi; }
    }

    float conf = sigm(to);
    float cx   = ((float)x + sigm(tx)) * t;
    float cy   = ((float)y + sigm(ty)) * t;
    float w_   = anc[a * 2 + 0] * expf(tw);
    float h_   = anc[a * 2 + 1] * expf(th);

    int n = NOFF + cell * 3 + a;
    float4* bp = (float4*)(g_boxes + ((size_t)b * NBOX + n) * 8);
    bp[0] = make_float4(cx - 0.5f * w_, cy - 0.5f * h_, cx + 0.5f * w_, cy + 0.5f * h_);
    bp[1] = make_float4(conf, (float)bcls, 0.0f, 0.0f);

    unsigned sk = (conf > 0.5f) ? (__float_as_uint(conf) | 0x80000000u) : 0x407FFFFFu;
    g_skey[(size_t)b * NBPAD + n] = sk;
    if (conf > 0.5f)
        atomicAdd(&g_hist[b * NBIN + ((sk >> 11) & 0xFFFu)], 1);
}

__global__ void __launch_bounds__(256)
decode_all_kernel(const float* __restrict__ o13, const float* __restrict__ o26,
                  const float* __restrict__ o52, const float* __restrict__ a13,
                  const float* __restrict__ a26, const float* __restrict__ a52)
{
    int gid = blockIdx.x * blockDim.x + threadIdx.x;
    if (gid >= TTOT) return;

    if (gid < T13)
        decode_scale<169, 13, 0>(o13, a13, gid, 32.0f);
    else if (gid < T13 + T26)
        decode_scale<676, 26, 507>(o26, a26, gid - T13, 16.0f);
    else
        decode_scale<2704, 52, 2535>(o52, a52, gid - T13 - T26, 8.0f);
}

// ======== K2: load hist + cumsum + scatter(u4) + rank + gather ========
// dyn smem: hist int[4096] @0, cum @16384, cumw @32768, sel u64[1024] @49152
#define K2_SMEM 57344

__global__ void __launch_bounds__(1024, 1)
select_rank_kernel(float* __restrict__ out)
{
    extern __shared__ char dyn[];
    int*                hist = (int*)dyn;
    int*                cum  = (int*)(dyn + 16384);
    int*                cumw = (int*)(dyn + 32768);
    unsigned long long* sel  = (unsigned long long*)(dyn + 49152);

    __shared__ int      wsum[32];
    __shared__ int      s_B;
    __shared__ unsigned validw[16];

    int b    = blockIdx.x;
    int tid  = threadIdx.x;
    int lane = tid & 31;
    int wid  = tid >> 5;

    // ---- load per-batch histogram (built by decode) ----
    const int* gh = g_hist + b * NBIN;
    #pragma unroll
    for (int i = tid; i < NBIN; i += 1024) hist[i] = gh[i];
    if (tid == 0) s_B = 0;
    if (tid < 16) validw[tid] = 0u;
    __syncthreads();

    // ---- descending exclusive cumsum + boundary bin ----
    {
        int hi = NBIN - 1 - 4 * tid;                // thread covers hi..hi-3 (desc)
        int h0 = hist[hi], h1 = hist[hi - 1], h2 = hist[hi - 2], h3 = hist[hi - 3];
        int s4 = h0 + h1 + h2 + h3;
        int pfx = s4;
        #pragma unroll
        for (int d = 1; d < 32; d <<= 1) {
            int v = __shfl_up_sync(0xffffffffu, pfx, d);
            if (lane >= d) pfx += v;
        }
        if (lane == 31) wsum[wid] = pfx;
        __syncthreads();
        if (tid < 32) {
            int v = wsum[lane];
            int p = v;
            #pragma unroll
            for (int d = 1; d < 32; d <<= 1) {
                int u = __shfl_up_sync(0xffffffffu, p, d);
                if (lane >= d) p += u;
            }
            wsum[lane] = p - v;                     // exclusive over warps
        }
        __syncthreads();
        int excl = wsum[wid] + (pfx - s4);          // # keys in bins > hi
        cum[hi]     = excl;                cumw[hi]     = excl;
        cum[hi - 1] = excl + h0;           cumw[hi - 1] = excl + h0;
        cum[hi - 2] = excl + h0 + h1;      cumw[hi - 2] = excl + h0 + h1;
        cum[hi - 3] = excl + h0 + h1 + h2; cumw[hi - 3] = excl + h0 + h1 + h2;
        if (excl < KTOP && excl + s4 >= KTOP) {
            int c = excl;
            if      (c + h0 >= KTOP)           s_B = hi;
            else if (c + h0 + h1 >= KTOP)      s_B = hi - 1;
            else if (c + h0 + h1 + h2 >= KTOP) s_B = hi - 2;
            else                               s_B = hi - 3;
        }
    }
    __syncthreads();
    int Bbin = s_B;

    // ---- scatter passing keys to bin-sorted slots (uint4 reads) ----
    const uint4* gk4 = (const uint4*)(g_skey + (size_t)b * NBPAD);
    for (int i4 = tid; i4 < NBPAD / 4; i4 += 1024) {
        uint4 kv = gk4[i4];
        int ib = i4 << 2;
        unsigned ks[4] = {kv.x, kv.y, kv.z, kv.w};
        #pragma unroll
        for (int u = 0; u < 4; ++u) {
            unsigned sk = ks[u];
            int i = ib + u;                          // i==NBOX pad has sk==0 -> fails
            if (sk > 0xBF000000u) {
                int bin = (sk >> 11) & 0xFFFu;
                if (bin >= Bbin) {
                    int slot = atomicAdd(&cumw[bin], 1);
                    if (slot < 1024)
                        sel[slot] = ((unsigned long long)sk << 32) |
                                    (unsigned long long)(0xFFFFFFFFu - (unsigned)i);
                }
            }
        }
    }
    __syncthreads();

    // ---- exact rank = base + intra-bin compares (avg ~1.3) + gather ----
    int C = cum[Bbin] + hist[Bbin];
    if (C > 1024) C = 1024;
    if (tid < C) {
        unsigned long long key = sel[tid];
        int bin  = (int)((key >> 43) & 0xFFFull);
        int base = cum[bin];
        int cnt  = hist[bin];
        int end  = base + cnt; if (end > 1024) end = 1024;
        int rank = base;
        for (int j = base; j < end; ++j) rank += (sel[j] > key);
        if (rank < KTOP) {
            unsigned idx = 0xFFFFFFFFu - (unsigned)(key & 0xFFFFFFFFull);
            const float4* sp = (const float4*)(g_boxes + ((size_t)b * NBOX + idx) * 8);
            float4 p0 = sp[0], p1 = sp[1];
            float* dst = out + ((size_t)b * KTOP + rank) * 7;
            dst[0] = p0.x; dst[1] = p0.y; dst[2] = p0.z; dst[3] = p0.w;
            dst[4] = p1.x; dst[5] = p1.y;
            if (p1.x > 0.5f) atomicOr(&validw[rank >> 5], 1u << (rank & 31));
        }
    }
    __syncthreads();
    if (tid < 16) g_valid[b * 16 + tid] = validw[tid];
}

// ======== K3: sup bitmatrix + greedy, one CTA per batch ========
__global__ void __launch_bounds__(1024, 1)
nms_kernel(float* __restrict__ out)
{
    __shared__ float sx1[KTOP], sy1[KTOP], sx2[KTOP], sy2[KTOP], sar[KTOP];
    __shared__ unsigned char scl[KTOP];
    __shared__ unsigned sup[KTOP * 16];     // 32 KB
    __shared__ unsigned validw[16], keepw[16];

    int b    = blockIdx.x;
    int tid  = threadIdx.x;
    int lane = tid & 31;
    const float* base_row = out + (size_t)b * KTOP * 7;

    if (tid < KTOP) {
        const float* r = base_row + (size_t)tid * 7;
        float x1 = r[0], y1 = r[1], x2 = r[2], y2 = r[3];
        sx1[tid] = x1; sy1[tid] = y1; sx2[tid] = x2; sy2[tid] = y2;
        sar[tid] = (x2 - x1) * (y2 - y1);
        scl[tid] = (unsigned char)(int)r[5];
    }
    if (tid < 16) { validw[tid] = g_valid[b * 16 + tid]; keepw[tid] = 0u; }
    __syncthreads();

    // ---- forward-only suppress bitmatrix (8 words/thread) ----
    #pragma unroll
    for (int w = tid; w < KTOP * 16; w += 1024) {
        int i  = w >> 4;
        int wj = w & 15;
        int j0 = wj << 5;
        unsigned fwd;
        if (j0 + 31 <= i)      fwd = 0u;
        else if (j0 > i)       fwd = 0xFFFFFFFFu;
        else                   fwd = 0xFFFFFFFFu << (i - j0 + 1);

        unsigned res = 0u;
        if (fwd) {
            unsigned ci4 = (unsigned)scl[i] * 0x01010101u;
            const unsigned* cp = (const unsigned*)(scl + j0);
            unsigned bits = 0u;
            #pragma unroll
            for (int qq = 0; qq < 8; ++qq) {
                unsigned eq = __vcmpeq4(cp[qq], ci4);
                unsigned bq = (((eq & 0x01010101u) * 0x01020408u) >> 24) & 0xFu;
                bits |= bq << (qq * 4);
            }
            bits &= fwd;
            if (bits) {
                float x1i = sx1[i], y1i = sy1[i], x2i = sx2[i], y2i = sy2[i];
                float ai  = sar[i];
                while (bits) {
                    int jj = __ffs(bits) - 1; bits &= bits - 1;
                    int j = j0 + jj;
                    float ix1 = fmaxf(x1i, sx1[j]);
                    float iy1 = fmaxf(y1i, sy1[j]);
                    float ix2 = fminf(x2i, sx2[j]);
                    float iy2 = fminf(y2i, sy2[j]);
                    float inter = fmaxf(ix2 - ix1, 0.0f) * fmaxf(iy2 - iy1, 0.0f);
                    float iou = inter / (ai + sar[j] - inter + 1e-9f);
                    if (iou > 0.3f) res |= 1u << jj;
                }
            }
        }
        sup[w] = res;
    }
    __syncthreads();

    // ---- chunked greedy scan (warp 0) ----
    if (tid < 32) {
        unsigned cand  = (lane < 16) ? validw[lane] : 0u;
        unsigned keepv = 0u;
        for (int blk = 0; blk < 16; ++blk) {
            unsigned cw = __shfl_sync(0xffffffffu, cand, blk);
            int base = blk << 5;
            unsigned rw = sup[(base + lane) * 16 + blk];   // row base+lane, word blk
            unsigned k32 = 0u;
            #pragma unroll 1
            for (int g = 0; g < 32; g += 8) {
                unsigned s0 = __shfl_sync(0xffffffffu, rw, g + 0);
                unsigned s1 = __shfl_sync(0xffffffffu, rw, g + 1);
                unsigned s2 = __shfl_sync(0xffffffffu, rw, g + 2);
                unsigned s3 = __shfl_sync(0xffffffffu, rw, g + 3);
                unsigned s4 = __shfl_sync(0xffffffffu, rw, g + 4);
                unsigned s5 = __shfl_sync(0xffffffffu, rw, g + 5);
                unsigned s6 = __shfl_sync(0xffffffffu, rw, g + 6);
                unsigned s7 = __shfl_sync(0xffffffffu, rw, g + 7);
                if (cw & (1u << (g + 0))) { k32 |= 1u << (g + 0); cw &= ~s0; }
                if (cw & (1u << (g + 1))) { k32 |= 1u << (g + 1); cw &= ~s1; }
                if (cw & (1u << (g + 2))) { k32 |= 1u << (g + 2); cw &= ~s2; }
                if (cw & (1u << (g + 3))) { k32 |= 1u << (g + 3); cw &= ~s3; }
                if (cw & (1u << (g + 4))) { k32 |= 1u << (g + 4); cw &= ~s4; }
                if (cw & (1u << (g + 5))) { k32 |= 1u << (g + 5); cw &= ~s5; }
                if (cw & (1u << (g + 6))) { k32 |= 1u << (g + 6); cw &= ~s6; }
                if (cw & (1u << (g + 7))) { k32 |= 1u << (g + 7); cw &= ~s7; }
            }
            // dense apply: 32 independent masked loads
            unsigned acc = 0u;
            if (lane < 16) {
                #pragma unroll
                for (int j = 0; j < 32; ++j) {
                    unsigned m = 0u - ((k32 >> j) & 1u);
                    acc |= sup[(base + j) * 16 + lane] & m;
                }
            }
            if (lane > blk && lane < 16) cand &= ~acc;
            if (lane == blk) keepv = k32;
        }
        if (lane < 16) keepw[lane] = keepv;
    }
    __syncthreads();

    if (tid < KTOP) {
        bool k = (keepw[tid >> 5] >> (tid & 31)) & 1u;
        out[((size_t)b * KTOP + tid) * 7 + 6] = k ? 1.0f : 0.0f;
    }

    // ---- restore g_hist=0 for the next (graph-replayed) run ----
    int* gh = g_hist + b * NBIN;
    #pragma unroll
    for (int i = tid; i < NBIN; i += 1024) gh[i] = 0;
}

// ---------------- launch ------------------------------------------
extern "C" void kernel_launch(void* const* d_in, const int* in_sizes, int n_in,
                              void* d_out, int out_size)
{
    const float* out13 = (const float*)d_in[0];
    const float* out26 = (const float*)d_in[1];
    const float* out52 = (const float*)d_in[2];
    const float* anc13 = (const float*)d_in[3];
    const float* anc26 = (const float*)d_in[4];
    const float* anc52 = (const float*)d_in[5];
    float* out = (float*)d_out;

    const int TPB = 256;
    decode_all_kernel<<<(TTOT + TPB - 1) / TPB, TPB>>>(out13, out26, out52,
                                                       anc13, anc26, anc52);

    static bool attr_set = false;
    if (!attr_set) {
        cudaFuncSetAttribute(select_rank_kernel,
                             cudaFuncAttributeMaxDynamicSharedMemorySize, K2_SMEM);
        attr_set = true;
    }
    select_rank_kernel<<<BATCH, 1024, K2_SMEM>>>(out);
    nms_kernel<<<BATCH, 1024>>>(out);
}

// round 12
// speedup vs baseline: 1.2210x; 1.0352x over previous
#include <cuda_runtime.h>
#include <stdint.h>
#include <math.h>

#define BATCH 32
#define NBOX  10647          // 507 + 2028 + 8112
#define NBPAD 10648          // padded stride (16B-aligned uint4 rows)
#define KTOP  512
#define NBIN  4096
#define TTOT  (BATCH * 3 * (169 + 676 + 2704))
#define T13   (BATCH * 3 * 169)
#define T26   (BATCH * 3 * 676)

// ---------------- scratch (no allocation allowed) ----------------
__device__ float    g_boxes[BATCH * NBOX * 8];  // x1,y1,x2,y2,conf,cls,pad,pad
__device__ unsigned g_skey [BATCH * NBPAD];     // mono32(score); pad elem stays 0
__device__ int      g_hist [BATCH * NBIN];      // zero at rest; decode fills, nms clears

__device__ __forceinline__ float sigm(float x) {
    return 1.0f / (1.0f + expf(-x));
}

// ---------------- compile-time specialized per-scale decode -------
template <int HW, int W, int NOFF>
__device__ __forceinline__ void decode_scale(const float* __restrict__ src,
                                             const float* __restrict__ anc,
                                             int r, float t)
{
    int b    = r / (3 * HW);
    int q    = r - b * 3 * HW;
    int a    = q / HW;
    int cell = q - a * HW;
    int y    = cell / W;
    int x    = cell - y * W;

    const float* p = src + ((size_t)b * 255 + (size_t)a * 85) * HW + cell;

    float tx = p[0];
    float ty = p[HW];
    float tw = p[2 * HW];
    float th = p[3 * HW];
    float to = p[4 * HW];

    // argmax over 80 classes, pairwise-tree per group of 8 (first-occurrence ties)
    const float* pc = p + 5 * HW;
    float best = -3.402823466e38f;
    int   bcls = 0;
    #pragma unroll
    for (int f = 0; f < 80; f += 8) {
        float v0 = pc[(f + 0) * HW];
        float v1 = pc[(f + 1) * HW];
        float v2 = pc[(f + 2) * HW];
        float v3 = pc[(f + 3) * HW];
        float v4 = pc[(f + 4) * HW];
        float v5 = pc[(f + 5) * HW];
        float v6 = pc[(f + 6) * HW];
        float v7 = pc[(f + 7) * HW];
        float m01v = (v1 > v0) ? v1 : v0;  int m01i = (v1 > v0) ? f + 1 : f + 0;
        float m23v = (v3 > v2) ? v3 : v2;  int m23i = (v3 > v2) ? f + 3 : f + 2;
        float m45v = (v5 > v4) ? v5 : v4;  int m45i = (v5 > v4) ? f + 5 : f + 4;
        float m67v = (v7 > v6) ? v7 : v6;  int m67i = (v7 > v6) ? f + 7 : f + 6;
        float a03v = (m23v > m01v) ? m23v : m01v;  int a03i = (m23v > m01v) ? m23i : m01i;
        float a47v = (m67v > m45v) ? m67v : m45v;  int a47i = (m67v > m45v) ? m67i : m45i;
        float gv   = (a47v > a03v) ? a47v : a03v;  int gi   = (a47v > a03v) ? a47i : a03i;
        if (gv > best) { best = gv; bcls = gi; }
    }

    float conf = sigm(to);
    float cx   = ((float)x + sigm(tx)) * t;
    float cy   = ((float)y + sigm(ty)) * t;
    float w_   = anc[a * 2 + 0] * expf(tw);
    float h_   = anc[a * 2 + 1] * expf(th);

    int n = NOFF + cell * 3 + a;
    float4* bp = (float4*)(g_boxes + ((size_t)b * NBOX + n) * 8);
    bp[0] = make_float4(cx - 0.5f * w_, cy - 0.5f * h_, cx + 0.5f * w_, cy + 0.5f * h_);
    bp[1] = make_float4(conf, (float)bcls, 0.0f, 0.0f);

    unsigned sk = (conf > 0.5f) ? (__float_as_uint(conf) | 0x80000000u) : 0x407FFFFFu;
    g_skey[(size_t)b * NBPAD + n] = sk;
    if (conf > 0.5f)
        atomicAdd(&g_hist[b * NBIN + ((sk >> 11) & 0xFFFu)], 1);
}

__global__ void __launch_bounds__(256)
decode_all_kernel(const float* __restrict__ o13, const float* __restrict__ o26,
                  const float* __restrict__ o52, const float* __restrict__ a13,
                  const float* __restrict__ a26, const float* __restrict__ a52)
{
    int gid = blockIdx.x * blockDim.x + threadIdx.x;
    if (gid >= TTOT) return;

    if (gid < T13)
        decode_scale<169, 13, 0>(o13, a13, gid, 32.0f);
    else if (gid < T13 + T26)
        decode_scale<676, 26, 507>(o26, a26, gid - T13, 16.0f);
    else
        decode_scale<2704, 52, 2535>(o52, a52, gid - T13 - T26, 8.0f);
}

// ======== fused tail: hist-load + cumsum + scatter + rank + sup + greedy ======
// dyn smem (sequential lifetimes):
//   [0,16384)      hist int[4096]     } live until end of rank
//   [16384,32768)  cum  int[4096]     }
//   [32768,49152)  cumw int[4096]
//   [49152,57344)  sel  u64[1024]
//   after rank:  sup u32[512*16] overlays [0,32768)
#define K2_SMEM 57344

__global__ void __launch_bounds__(1024, 1)
nms_kernel(float* __restrict__ out)
{
    extern __shared__ char dyn[];
    int*                hist = (int*)dyn;
    int*                cum  = (int*)(dyn + 16384);
    int*                cumw = (int*)(dyn + 32768);
    unsigned long long* sel  = (unsigned long long*)(dyn + 49152);
    unsigned*           sup  = (unsigned*)dyn;          // overlays hist+cum after rank

    __shared__ float sx1[KTOP], sy1[KTOP], sx2[KTOP], sy2[KTOP], sar[KTOP];
    __shared__ unsigned char scl[KTOP];
    __shared__ int      wsum[32];
    __shared__ int      s_B;
    __shared__ unsigned validw[16], keepw[16];

    int b    = blockIdx.x;
    int tid  = threadIdx.x;
    int lane = tid & 31;
    int wid  = tid >> 5;

    // ---- load per-batch histogram (built by decode) ----
    const int* gh = g_hist + b * NBIN;
    #pragma unroll
    for (int i = tid; i < NBIN; i += 1024) hist[i] = gh[i];
    if (tid == 0) s_B = 0;
    if (tid < 16) { validw[tid] = 0u; keepw[tid] = 0u; }
    __syncthreads();

    // ---- descending exclusive cumsum + boundary bin ----
    {
        int hi = NBIN - 1 - 4 * tid;                // thread covers hi..hi-3 (desc)
        int h0 = hist[hi], h1 = hist[hi - 1], h2 = hist[hi - 2], h3 = hist[hi - 3];
        int s4 = h0 + h1 + h2 + h3;
        int pfx = s4;
        #pragma unroll
        for (int d = 1; d < 32; d <<= 1) {
            int v = __shfl_up_sync(0xffffffffu, pfx, d);
            if (lane >= d) pfx += v;
        }
        if (lane == 31) wsum[wid] = pfx;
        __syncthreads();
        if (tid < 32) {
            int v = wsum[lane];
            int p = v;
            #pragma unroll
            for (int d = 1; d < 32; d <<= 1) {
                int u = __shfl_up_sync(0xffffffffu, p, d);
                if (lane >= d) p += u;
            }
            wsum[lane] = p - v;                     // exclusive over warps
        }
        __syncthreads();
        int excl = wsum[wid] + (pfx - s4);          // # keys in bins > hi
        cum[hi]     = excl;                cumw[hi]     = excl;
        cum[hi - 1] = excl + h0;           cumw[hi - 1] = excl + h0;
        cum[hi - 2] = excl + h0 + h1;      cumw[hi - 2] = excl + h0 + h1;
        cum[hi - 3] = excl + h0 + h1 + h2; cumw[hi - 3] = excl + h0 + h1 + h2;
        if (excl < KTOP && excl + s4 >= KTOP) {
            int c = excl;
            if      (c + h0 >= KTOP)           s_B = hi;
            else if (c + h0 + h1 >= KTOP)      s_B = hi - 1;
            else if (c + h0 + h1 + h2 >= KTOP) s_B = hi - 2;
            else                               s_B = hi - 3;
        }
    }
    __syncthreads();
    int Bbin = s_B;

    // ---- scatter passing keys to bin-sorted slots (uint4 reads) ----
    const uint4* gk4 = (const uint4*)(g_skey + (size_t)b * NBPAD);
    for (int i4 = tid; i4 < NBPAD / 4; i4 += 1024) {
        uint4 kv = gk4[i4];
        int ib = i4 << 2;
        unsigned ks[4] = {kv.x, kv.y, kv.z, kv.w};
        #pragma unroll
        for (int u = 0; u < 4; ++u) {
            unsigned sk = ks[u];
            int i = ib + u;                          // i==NBOX pad has sk==0 -> fails
            if (sk > 0xBF000000u) {
                int bin = (sk >> 11) & 0xFFFu;
                if (bin >= Bbin) {
                    int slot = atomicAdd(&cumw[bin], 1);
                    if (slot < 1024)
                        sel[slot] = ((unsigned long long)sk << 32) |
                                    (unsigned long long)(0xFFFFFFFFu - (unsigned)i);
                }
            }
        }
    }
    __syncthreads();

    // ---- exact rank = base + intra-bin compares (avg ~1.3) + gather ----
    int C = cum[Bbin] + hist[Bbin];
    if (C > 1024) C = 1024;
    if (tid < C) {
        unsigned long long key = sel[tid];
        int bin  = (int)((key >> 43) & 0xFFFull);
        int base = cum[bin];
        int cnt  = hist[bin];
        int end  = base + cnt; if (end > 1024) end = 1024;
        int rank = base;
        for (int j = base; j < end; ++j) rank += (sel[j] > key);
        if (rank < KTOP) {
            unsigned idx = 0xFFFFFFFFu - (unsigned)(key & 0xFFFFFFFFull);
            const float4* sp = (const float4*)(g_boxes + ((size_t)b * NBOX + idx) * 8);
            float4 p0 = sp[0], p1 = sp[1];
            sx1[rank] = p0.x; sy1[rank] = p0.y; sx2[rank] = p0.z; sy2[rank] = p0.w;
            sar[rank] = (p0.z - p0.x) * (p0.w - p0.y);
            scl[rank] = (unsigned char)(int)p1.y;
            float* dst = out + ((size_t)b * KTOP + rank) * 7;
            dst[0] = p0.x; dst[1] = p0.y; dst[2] = p0.z; dst[3] = p0.w;
            dst[4] = p1.x; dst[5] = p1.y;
            if (p1.x > 0.5f) atomicOr(&validw[rank >> 5], 1u << (rank & 31));
        }
    }
    __syncthreads();     // hist/cum/sel dead past here; sup overlays them

    // ---- forward-only suppress bitmatrix (8 words/thread) ----
    #pragma unroll
    for (int w = tid; w < KTOP * 16; w += 1024) {
        int i  = w >> 4;
        int wj = w & 15;
        int j0 = wj << 5;
        unsigned fwd;
        if (j0 + 31 <= i)      fwd = 0u;
        else if (j0 > i)       fwd = 0xFFFFFFFFu;
        else                   fwd = 0xFFFFFFFFu << (i - j0 + 1);

        unsigned res = 0u;
        if (fwd) {
            unsigned ci4 = (unsigned)scl[i] * 0x01010101u;
            const unsigned* cp = (const unsigned*)(scl + j0);
            unsigned bits = 0u;
            #pragma unroll
            for (int qq = 0; qq < 8; ++qq) {
                unsigned eq = __vcmpeq4(cp[qq], ci4);
                unsigned bq = (((eq & 0x01010101u) * 0x01020408u) >> 24) & 0xFu;
                bits |= bq << (qq * 4);
            }
            bits &= fwd;
            if (bits) {
                float x1i = sx1[i], y1i = sy1[i], x2i = sx2[i], y2i = sy2[i];
                float ai  = sar[i];
                while (bits) {
                    int jj = __ffs(bits) - 1; bits &= bits - 1;
                    int j = j0 + jj;
                    float ix1 = fmaxf(x1i, sx1[j]);
                    float iy1 = fmaxf(y1i, sy1[j]);
                    float ix2 = fminf(x2i, sx2[j]);
                    float iy2 = fminf(y2i, sy2[j]);
                    float inter = fmaxf(ix2 - ix1, 0.0f) * fmaxf(iy2 - iy1, 0.0f);
                    float iou = inter / (ai + sar[j] - inter + 1e-9f);
                    if (iou > 0.3f) res |= 1u << jj;
                }
            }
        }
        sup[w] = res;
    }
    __syncthreads();

    // ---- chunked greedy scan (warp 0) ----
    if (tid < 32) {
        unsigned cand  = (lane < 16) ? validw[lane] : 0u;
        unsigned keepv = 0u;
        for (int blk = 0; blk < 16; ++blk) {
            unsigned cw = __shfl_sync(0xffffffffu, cand, blk);
            int base = blk << 5;
            unsigned rw = sup[(base + lane) * 16 + blk];   // row base+lane, word blk
            unsigned k32 = 0u;
            #pragma unroll 1
            for (int g = 0; g < 32; g += 8) {
                unsigned s0 = __shfl_sync(0xffffffffu, rw, g + 0);
                unsigned s1 = __shfl_sync(0xffffffffu, rw, g + 1);
                unsigned s2 = __shfl_sync(0xffffffffu, rw, g + 2);
                unsigned s3 = __shfl_sync(0xffffffffu, rw, g + 3);
                unsigned s4 = __shfl_sync(0xffffffffu, rw, g + 4);
                unsigned s5 = __shfl_sync(0xffffffffu, rw, g + 5);
                unsigned s6 = __shfl_sync(0xffffffffu, rw, g + 6);
                unsigned s7 = __shfl_sync(0xffffffffu, rw, g + 7);
                if (cw & (1u << (g + 0))) { k32 |= 1u << (g + 0); cw &= ~s0; }
                if (cw & (1u << (g + 1))) { k32 |= 1u << (g + 1); cw &= ~s1; }
                if (cw & (1u << (g + 2))) { k32 |= 1u << (g + 2); cw &= ~s2; }
                if (cw & (1u << (g + 3))) { k32 |= 1u << (g + 3); cw &= ~s3; }
                if (cw & (1u << (g + 4))) { k32 |= 1u << (g + 4); cw &= ~s4; }
                if (cw & (1u << (g + 5))) { k32 |= 1u << (g + 5); cw &= ~s5; }
                if (cw & (1u << (g + 6))) { k32 |= 1u << (g + 6); cw &= ~s6; }
                if (cw & (1u << (g + 7))) { k32 |= 1u << (g + 7); cw &= ~s7; }
            }
            // dense apply: 32 independent masked loads
            unsigned acc = 0u;
            if (lane < 16) {
                #pragma unroll
                for (int j = 0; j < 32; ++j) {
                    unsigned m = 0u - ((k32 >> j) & 1u);
                    acc |= sup[(base + j) * 16 + lane] & m;
                }
            }
            if (lane > blk && lane < 16) cand &= ~acc;
            if (lane == blk) keepv = k32;
        }
        if (lane < 16) keepw[lane] = keepv;
    }
    __syncthreads();

    if (tid < KTOP) {
        bool k = (keepw[tid >> 5] >> (tid & 31)) & 1u;
        out[((size_t)b * KTOP + tid) * 7 + 6] = k ? 1.0f : 0.0f;
    }

    // ---- restore g_hist=0 for the next (graph-replayed) run ----
    int* ghw = g_hist + b * NBIN;
    #pragma unroll
    for (int i = tid; i < NBIN; i += 1024) ghw[i] = 0;
}

// ---------------- launch ------------------------------------------
extern "C" void kernel_launch(void* const* d_in, const int* in_sizes, int n_in,
                              void* d_out, int out_size)
{
    const float* out13 = (const float*)d_in[0];
    const float* out26 = (const float*)d_in[1];
    const float* out52 = (const float*)d_in[2];
    const float* anc13 = (const float*)d_in[3];
    const float* anc26 = (const float*)d_in[4];
    const float* anc52 = (const float*)d_in[5];
    float* out = (float*)d_out;

    const int TPB = 256;
    decode_all_kernel<<<(TTOT + TPB - 1) / TPB, TPB>>>(out13, out26, out52,
                                                       anc13, anc26, anc52);

    static bool attr_set = false;
    if (!attr_set) {
        cudaFuncSetAttribute(nms_kernel,
                             cudaFuncAttributeMaxDynamicSharedMemorySize, K2_SMEM);
        attr_set = true;
    }
    nms_kernel<<<BATCH, 1024, K2_SMEM>>>(out);
}

// round 14
// speedup vs baseline: 1.4071x; 1.1524x over previous
#include <cuda_runtime.h>
#include <stdint.h>
#include <math.h>

#define BATCH 32
#define NBOX  10647          // 507 + 2028 + 8112
#define NBPAD 10648          // padded stride (16B-aligned uint4 rows)
#define KTOP  512
#define NBIN  4096
#define NCLS  80
#define CCAP  64             // per-class bucket capacity (avg 6.4, P(>64)~0)
#define TTOT  (BATCH * 3 * (169 + 676 + 2704))
#define T13   (BATCH * 3 * 169)
#define T26   (BATCH * 3 * 676)

// ---------------- scratch (no allocation allowed) ----------------
__device__ float    g_boxes[BATCH * NBOX * 8];  // x1,y1,x2,y2,conf,cls,pad,pad
__device__ unsigned g_skey [BATCH * NBPAD];     // mono32(score); pad elem stays 0
__device__ int      g_hist [BATCH * NBIN];      // zero at rest; decode fills, nms clears

__device__ __forceinline__ float sigm(float x) {
    return 1.0f / (1.0f + expf(-x));
}

// ---------------- compile-time specialized per-scale decode -------
template <int HW, int W, int NOFF>
__device__ __forceinline__ void decode_scale(const float* __restrict__ src,
                                             const float* __restrict__ anc,
                                             int r, float t)
{
    int b    = r / (3 * HW);
    int q    = r - b * 3 * HW;
    int a    = q / HW;
    int cell = q - a * HW;
    int y    = cell / W;
    int x    = cell - y * W;

    const float* p = src + ((size_t)b * 255 + (size_t)a * 85) * HW + cell;

    float tx = __ldcs(p);
    float ty = __ldcs(p + HW);
    float tw = __ldcs(p + 2 * HW);
    float th = __ldcs(p + 3 * HW);
    float to = __ldcs(p + 4 * HW);

    // argmax over 80 classes, pairwise-tree per group of 8 (first-occurrence ties)
    const float* pc = p + 5 * HW;
    float best = -3.402823466e38f;
    int   bcls = 0;
    #pragma unroll
    for (int f = 0; f < 80; f += 8) {
        float v0 = __ldcs(pc + (f + 0) * HW);
        float v1 = __ldcs(pc + (f + 1) * HW);
        float v2 = __ldcs(pc + (f + 2) * HW);
        float v3 = __ldcs(pc + (f + 3) * HW);
        float v4 = __ldcs(pc + (f + 4) * HW);
        float v5 = __ldcs(pc + (f + 5) * HW);
        float v6 = __ldcs(pc + (f + 6) * HW);
        float v7 = __ldcs(pc + (f + 7) * HW);
        float m01v = (v1 > v0) ? v1 : v0;  int m01i = (v1 > v0) ? f + 1 : f + 0;
        float m23v = (v3 > v2) ? v3 : v2;  int m23i = (v3 > v2) ? f + 3 : f + 2;
        float m45v = (v5 > v4) ? v5 : v4;  int m45i = (v5 > v4) ? f + 5 : f + 4;
        float m67v = (v7 > v6) ? v7 : v6;  int m67i = (v7 > v6) ? f + 7 : f + 6;
        float a03v = (m23v > m01v) ? m23v : m01v;  int a03i = (m23v > m01v) ? m23i : m01i;
        float a47v = (m67v > m45v) ? m67v : m45v;  int a47i = (m67v > m45v) ? m67i : m45i;
        float gv   = (a47v > a03v) ? a47v : a03v;  int gi   = (a47v > a03v) ? a47i : a03i;
        if (gv > best) { best = gv; bcls = gi; }
    }

    float conf = sigm(to);
    float cx   = ((float)x + sigm(tx)) * t;
    float cy   = ((float)y + sigm(ty)) * t;
    float w_   = anc[a * 2 + 0] * expf(tw);
    float h_   = anc[a * 2 + 1] * expf(th);

    int n = NOFF + cell * 3 + a;
    float4* bp = (float4*)(g_boxes + ((size_t)b * NBOX + n) * 8);
    __stcs(bp,     make_float4(cx - 0.5f * w_, cy - 0.5f * h_, cx + 0.5f * w_, cy + 0.5f * h_));
    __stcs(bp + 1, make_float4(conf, (float)bcls, 0.0f, 0.0f));

    unsigned sk = (conf > 0.5f) ? (__float_as_uint(conf) | 0x80000000u) : 0x407FFFFFu;
    g_skey[(size_t)b * NBPAD + n] = sk;
    if (conf > 0.5f)
        atomicAdd(&g_hist[b * NBIN + ((sk >> 11) & 0xFFFu)], 1);
}

__global__ void __launch_bounds__(256)
decode_all_kernel(const float* __restrict__ o13, const float* __restrict__ o26,
                  const float* __restrict__ o52, const float* __restrict__ a13,
                  const float* __restrict__ a26, const float* __restrict__ a52)
{
    int gid = blockIdx.x * blockDim.x + threadIdx.x;
    if (gid >= TTOT) return;

    if (gid < T13)
        decode_scale<169, 13, 0>(o13, a13, gid, 32.0f);
    else if (gid < T13 + T26)
        decode_scale<676, 26, 507>(o26, a26, gid - T13, 16.0f);
    else
        decode_scale<2704, 52, 2535>(o52, a52, gid - T13 - T26, 8.0f);
}

// ======== fused tail: hist-load + cumsum + scatter + rank + sup + greedy ======
// dyn smem (sequential lifetimes):
//   [0,16384)      hist int[4096]     } live until end of rank
//   [16384,32768)  cum  int[4096]     }
//   [32768,49152)  cumw int[4096]     } cumw dead after scatter
//   [49152,57344)  sel  u64[1024]
//   after rank:  sup u32[512*16] overlays [0,32768)
//                cls_list u16[80*64] overlays [32768,43008)
#define K2_SMEM 57344

__global__ void __launch_bounds__(1024, 1)
nms_kernel(float* __restrict__ out)
{
    extern __shared__ char dyn[];
    int*                hist = (int*)dyn;
    int*                cum  = (int*)(dyn + 16384);
    int*                cumw = (int*)(dyn + 32768);
    unsigned long long* sel  = (unsigned long long*)(dyn + 49152);
    unsigned*           sup  = (unsigned*)dyn;                    // overlays hist+cum
    unsigned short*     clist = (unsigned short*)(dyn + 32768);   // overlays cumw

    __shared__ float sx1[KTOP], sy1[KTOP], sx2[KTOP], sy2[KTOP], sar[KTOP];
    __shared__ unsigned char scl[KTOP];
    __shared__ int      ccnt[NCLS];
    __shared__ int      wsum[32];
    __shared__ int      s_B;
    __shared__ unsigned validw[16], keepw[16];

    int b    = blockIdx.x;
    int tid  = threadIdx.x;
    int lane = tid & 31;
    int wid  = tid >> 5;

    // ---- load per-batch histogram (built by decode) ----
    const int* gh = g_hist + b * NBIN;
    #pragma unroll
    for (int i = tid; i < NBIN; i += 1024) hist[i] = gh[i];
    if (tid == 0) s_B = 0;
    if (tid < 16) { validw[tid] = 0u; keepw[tid] = 0u; }
    if (tid < NCLS) ccnt[tid] = 0;
    __syncthreads();

    // ---- descending exclusive cumsum + boundary bin ----
    {
        int hi = NBIN - 1 - 4 * tid;                // thread covers hi..hi-3 (desc)
        int h0 = hist[hi], h1 = hist[hi - 1], h2 = hist[hi - 2], h3 = hist[hi - 3];
        int s4 = h0 + h1 + h2 + h3;
        int pfx = s4;
        #pragma unroll
        for (int d = 1; d < 32; d <<= 1) {
            int v = __shfl_up_sync(0xffffffffu, pfx, d);
            if (lane >= d) pfx += v;
        }
        if (lane == 31) wsum[wid] = pfx;
        __syncthreads();
        if (tid < 32) {
            int v = wsum[lane];
            int p = v;
            #pragma unroll
            for (int d = 1; d < 32; d <<= 1) {
                int u = __shfl_up_sync(0xffffffffu, p, d);
                if (lane >= d) p += u;
            }
            wsum[lane] = p - v;                     // exclusive over warps
        }
        __syncthreads();
        int excl = wsum[wid] + (pfx - s4);          // # keys in bins > hi
        cum[hi]     = excl;                cumw[hi]     = excl;
        cum[hi - 1] = excl + h0;           cumw[hi - 1] = excl + h0;
        cum[hi - 2] = excl + h0 + h1;      cumw[hi - 2] = excl + h0 + h1;
        cum[hi - 3] = excl + h0 + h1 + h2; cumw[hi - 3] = excl + h0 + h1 + h2;
        if (excl < KTOP && excl + s4 >= KTOP) {
            int c = excl;
            if      (c + h0 >= KTOP)           s_B = hi;
            else if (c + h0 + h1 >= KTOP)      s_B = hi - 1;
            else if (c + h0 + h1 + h2 >= KTOP) s_B = hi - 2;
            else                               s_B = hi - 3;
        }
    }
    __syncthreads();
    int Bbin = s_B;

    // ---- scatter passing keys to bin-sorted slots (uint4 reads) ----
    const uint4* gk4 = (const uint4*)(g_skey + (size_t)b * NBPAD);
    for (int i4 = tid; i4 < NBPAD / 4; i4 += 1024) {
        uint4 kv = gk4[i4];
        int ib = i4 << 2;
        unsigned ks[4] = {kv.x, kv.y, kv.z, kv.w};
        #pragma unroll
        for (int u = 0; u < 4; ++u) {
            unsigned sk = ks[u];
            int i = ib + u;                          // i==NBOX pad has sk==0 -> fails
            if (sk > 0xBF000000u) {
                int bin = (sk >> 11) & 0xFFFu;
                if (bin >= Bbin) {
                    int slot = atomicAdd(&cumw[bin], 1);
                    if (slot < 1024)
                        sel[slot] = ((unsigned long long)sk << 32) |
                                    (unsigned long long)(0xFFFFFFFFu - (unsigned)i);
                }
            }
        }
    }
    __syncthreads();

    // ---- exact rank = base + intra-bin compares (avg ~1.3) + gather ----
    int C = cum[Bbin] + hist[Bbin];
    if (C > 1024) C = 1024;
    if (tid < C) {
        unsigned long long key = sel[tid];
        int bin  = (int)((key >> 43) & 0xFFFull);
        int base = cum[bin];
        int cnt  = hist[bin];
        int end  = base + cnt; if (end > 1024) end = 1024;
        int rank = base;
        for (int j = base; j < end; ++j) rank += (sel[j] > key);
        if (rank < KTOP) {
            unsigned idx = 0xFFFFFFFFu - (unsigned)(key & 0xFFFFFFFFull);
            const float4* sp = (const float4*)(g_boxes + ((size_t)b * NBOX + idx) * 8);
            float4 p0 = sp[0], p1 = sp[1];
            sx1[rank] = p0.x; sy1[rank] = p0.y; sx2[rank] = p0.z; sy2[rank] = p0.w;
            sar[rank] = (p0.z - p0.x) * (p0.w - p0.y);
            int cls = (int)p1.y;
            scl[rank] = (unsigned char)cls;
            float* dst = out + ((size_t)b * KTOP + rank) * 7;
            dst[0] = p0.x; dst[1] = p0.y; dst[2] = p0.z; dst[3] = p0.w;
            dst[4] = p1.x; dst[5] = p1.y;
            if (p1.x > 0.5f) atomicOr(&validw[rank >> 5], 1u << (rank & 31));
        }
    }
    __syncthreads();     // hist/cum/cumw/sel dead past here; sup + clist overlay them

    // ---- class buckets: append each rank to its class list ----
    if (tid < KTOP) {
        int c = scl[tid];
        int pos = atomicAdd(&ccnt[c], 1);
        if (pos < CCAP) clist[c * CCAP + pos] = (unsigned short)tid;
    }
    __syncthreads();

    // ---- sup rows: thread i owns row i; scan only its class bucket (j>i) ----
    if (tid < KTOP) {
        unsigned row[16];
        #pragma unroll
        for (int w = 0; w < 16; ++w) row[w] = 0u;

        int c   = scl[tid];
        int cnt = ccnt[c]; if (cnt > CCAP) cnt = CCAP;
        float x1i = sx1[tid], y1i = sy1[tid], x2i = sx2[tid], y2i = sy2[tid];
        float ai  = sar[tid];
        const unsigned short* lst = clist + c * CCAP;
        for (int k = 0; k < cnt; ++k) {
            int j = lst[k];
            if (j > tid) {
                float ix1 = fmaxf(x1i, sx1[j]);
                float iy1 = fmaxf(y1i, sy1[j]);
                float ix2 = fminf(x2i, sx2[j]);
                float iy2 = fminf(y2i, sy2[j]);
                float inter = fmaxf(ix2 - ix1, 0.0f) * fmaxf(iy2 - iy1, 0.0f);
                float iou = inter / (ai + sar[j] - inter + 1e-9f);
                if (iou > 0.3f) row[j >> 5] |= 1u << (j & 31);
            }
        }
        #pragma unroll
        for (int w = 0; w < 16; ++w) sup[tid * 16 + w] = row[w];
    }
    __syncthreads();

    // ---- chunked greedy scan (warp 0) ----
    if (tid < 32) {
        unsigned cand  = (lane < 16) ? validw[lane] : 0u;
        unsigned keepv = 0u;
        for (int blk = 0; blk < 16; ++blk) {
            unsigned cw = __shfl_sync(0xffffffffu, cand, blk);
            int base = blk << 5;
            unsigned rw = sup[(base + lane) * 16 + blk];   // row base+lane, word blk
            unsigned k32 = 0u;
            #pragma unroll 1
            for (int g = 0; g < 32; g += 8) {
                unsigned s0 = __shfl_sync(0xffffffffu, rw, g + 0);
                unsigned s1 = __shfl_sync(0xffffffffu, rw, g + 1);
                unsigned s2 = __shfl_sync(0xffffffffu, rw, g + 2);
                unsigned s3 = __shfl_sync(0xffffffffu, rw, g + 3);
                unsigned s4 = __shfl_sync(0xffffffffu, rw, g + 4);
                unsigned s5 = __shfl_sync(0xffffffffu, rw, g + 5);
                unsigned s6 = __shfl_sync(0xffffffffu, rw, g + 6);
                unsigned s7 = __shfl_sync(0xffffffffu, rw, g + 7);
                if (cw & (1u << (g + 0))) { k32 |= 1u << (g + 0); cw &= ~s0; }
                if (cw & (1u << (g + 1))) { k32 |= 1u << (g + 1); cw &= ~s1; }
                if (cw & (1u << (g + 2))) { k32 |= 1u << (g + 2); cw &= ~s2; }
                if (cw & (1u << (g + 3))) { k32 |= 1u << (g + 3); cw &= ~s3; }
                if (cw & (1u << (g + 4))) { k32 |= 1u << (g + 4); cw &= ~s4; }
                if (cw & (1u << (g + 5))) { k32 |= 1u << (g + 5); cw &= ~s5; }
                if (cw & (1u << (g + 6))) { k32 |= 1u << (g + 6); cw &= ~s6; }
                if (cw & (1u << (g + 7))) { k32 |= 1u << (g + 7); cw &= ~s7; }
            }
            // dense apply: 32 independent masked loads
            unsigned acc = 0u;
            if (lane < 16) {
                #pragma unroll
                for (int j = 0; j < 32; ++j) {
                    unsigned m = 0u - ((k32 >> j) & 1u);
                    acc |= sup[(base + j) * 16 + lane] & m;
                }
            }
            if (lane > blk && lane < 16) cand &= ~acc;
            if (lane == blk) keepv = k32;
        }
        if (lane < 16) keepw[lane] = keepv;
    }
    __syncthreads();

    if (tid < KTOP) {
        bool k = (keepw[tid >> 5] >> (tid & 31)) & 1u;
        out[((size_t)b * KTOP + tid) * 7 + 6] = k ? 1.0f : 0.0f;
    }

    // ---- restore g_hist=0 for the next (graph-replayed) run ----
    int* ghw = g_hist + b * NBIN;
    #pragma unroll
    for (int i = tid; i < NBIN; i += 1024) ghw[i] = 0;
}

// ---------------- launch ------------------------------------------
extern "C" void kernel_launch(void* const* d_in, const int* in_sizes, int n_in,
                              void* d_out, int out_size)
{
    const float* out13 = (const float*)d_in[0];
    const float* out26 = (const float*)d_in[1];
    const float* out52 = (const float*)d_in[2];
    const float* anc13 = (const float*)d_in[3];
    const float* anc26 = (const float*)d_in[4];
    const float* anc52 = (const float*)d_in[5];
    float* out = (float*)d_out;

    const int TPB = 256;
    decode_all_kernel<<<(TTOT + TPB - 1) / TPB, TPB>>>(out13, out26, out52,
                                                       anc13, anc26, anc52);

    static bool attr_set = false;
    if (!attr_set) {
        cudaFuncSetAttribute(nms_kernel,
                             cudaFuncAttributeMaxDynamicSharedMemorySize, K2_SMEM);
        attr_set = true;
    }
    nms_kernel<<<BATCH, 1024, K2_SMEM>>>(out);
}